// round 2
// baseline (speedup 1.0000x reference)
#include <cuda_runtime.h>
#include <cuda_bf16.h>
#include <cstdint>

// ---------------- problem constants ----------------
#define NF_DIM 8192
#define NX_DIM 2048
#define M_DIM  8192           // 4*2048 rows of x
#define KP     4096           // panel K: [hi(2048) | lo(2048)]
#define BM 128
#define BN 128
#define BK 64
#define NSTAGE 3
#define NITER  (NX_DIM / BK)  // 32 macro K-chunks

#define SMEM_STAGE 65536      // 4 tiles x 16KB (Ahi, Alo, Bhi, Blo)
#define SMEM_BYTES (NSTAGE * SMEM_STAGE + 1024)

// ---------------- scratch (device globals; no cudaMalloc allowed) ----------------
static __device__ __align__(256) __nv_bfloat16 g_A[(size_t)M_DIM * KP];   // [x_hi | x_lo]
static __device__ __align__(256) __nv_bfloat16 g_B[(size_t)NF_DIM * KP];  // [W_hi | W_lo]

// ---------------- helpers ----------------
static __device__ __forceinline__ uint32_t smem_u32(const void* p) {
    uint32_t a;
    asm("{ .reg .u64 t; cvta.to.shared.u64 t, %1; cvt.u32.u64 %0, t; }" : "=r"(a) : "l"(p));
    return a;
}
#define SWZ(o) ((o) ^ ((((uint32_t)(o)) >> 3) & 0x70u))

static __device__ __forceinline__ void cpasync16(uint32_t s, const void* g) {
    asm volatile("cp.async.cg.shared.global [%0], [%1], 16;" :: "r"(s), "l"(g));
}
static __device__ __forceinline__ void cp_commit() {
    asm volatile("cp.async.commit_group;" ::: "memory");
}
static __device__ __forceinline__ void cp_wait1() {
    asm volatile("cp.async.wait_group 1;" ::: "memory");
}
static __device__ __forceinline__ void ldm4(uint32_t* r, uint32_t addr) {
    asm volatile("ldmatrix.sync.aligned.m8n8.x4.shared.b16 {%0,%1,%2,%3}, [%4];"
                 : "=r"(r[0]), "=r"(r[1]), "=r"(r[2]), "=r"(r[3]) : "r"(addr));
}
static __device__ __forceinline__ void mma16816(float* c, const uint32_t* a, uint32_t b0, uint32_t b1) {
    asm volatile(
        "mma.sync.aligned.m16n8k16.row.col.f32.bf16.bf16.f32 "
        "{%0,%1,%2,%3}, {%4,%5,%6,%7}, {%8,%9}, {%0,%1,%2,%3};"
        : "+f"(c[0]), "+f"(c[1]), "+f"(c[2]), "+f"(c[3])
        : "r"(a[0]), "r"(a[1]), "r"(a[2]), "r"(a[3]), "r"(b0), "r"(b1));
}

// ---------------- prep kernel 1: split x into bf16 hi/lo panels ----------------
__global__ void prep_x_kernel(const float* __restrict__ x) {
    size_t i = ((size_t)blockIdx.x * blockDim.x + threadIdx.x) * 4;
    float4 v = *(const float4*)(x + i);
    size_t m = i >> 11;           // row (K = 2048)
    int    k = (int)(i & 2047);

    __nv_bfloat16 h0 = __float2bfloat16_rn(v.x);
    __nv_bfloat16 h1 = __float2bfloat16_rn(v.y);
    __nv_bfloat16 h2 = __float2bfloat16_rn(v.z);
    __nv_bfloat16 h3 = __float2bfloat16_rn(v.w);
    __nv_bfloat16 l0 = __float2bfloat16_rn(v.x - __bfloat162float(h0));
    __nv_bfloat16 l1 = __float2bfloat16_rn(v.y - __bfloat162float(h1));
    __nv_bfloat16 l2 = __float2bfloat16_rn(v.z - __bfloat162float(h2));
    __nv_bfloat16 l3 = __float2bfloat16_rn(v.w - __bfloat162float(h3));

    __nv_bfloat16* row = g_A + m * (size_t)KP;
    __nv_bfloat162 hA; hA.x = h0; hA.y = h1;
    __nv_bfloat162 hB; hB.x = h2; hB.y = h3;
    __nv_bfloat162 lA; lA.x = l0; lA.y = l1;
    __nv_bfloat162 lB; lB.x = l2; lB.y = l3;
    *(__nv_bfloat162*)(row + k)            = hA;
    *(__nv_bfloat162*)(row + k + 2)        = hB;
    *(__nv_bfloat162*)(row + 2048 + k)     = lA;
    *(__nv_bfloat162*)(row + 2048 + k + 2) = lB;
}

// ---------------- prep kernel 2: dequant W into bf16 hi/lo panels ----------------
__global__ void prep_w_kernel(const int* __restrict__ packed,
                              const float* __restrict__ scales,
                              const int* __restrict__ zeros) {
    size_t i = (size_t)blockIdx.x * blockDim.x + threadIdx.x;  // 0 .. 8192*1024-1
    int n = (int)(i >> 10);
    int j = (int)(i & 1023);
    int p = packed[i];
    int g = j >> 5;                     // group of k0 = 2j (64 elems per group)
    float s = scales[n * 32 + g];
    float z = (float)zeros[n * 32 + g];
    float w0 = (float)(p & 15) * s - z * s;        // low nibble -> even k
    float w1 = (float)((p >> 4) & 15) * s - z * s; // high nibble -> odd k

    __nv_bfloat16 h0 = __float2bfloat16_rn(w0);
    __nv_bfloat16 h1 = __float2bfloat16_rn(w1);
    __nv_bfloat16 l0 = __float2bfloat16_rn(w0 - __bfloat162float(h0));
    __nv_bfloat16 l1 = __float2bfloat16_rn(w1 - __bfloat162float(h1));

    __nv_bfloat16* row = g_B + (size_t)n * KP;
    int k = 2 * j;
    __nv_bfloat162 hh; hh.x = h0; hh.y = h1;
    __nv_bfloat162 ll; ll.x = l0; ll.y = l1;
    *(__nv_bfloat162*)(row + k)        = hh;
    *(__nv_bfloat162*)(row + 2048 + k) = ll;
}

// ---------------- GEMM: D = A @ B^T + bias, 3-pass bf16-split HMMA ----------------
// 256 threads = 8 warps, warp grid 2(M) x 4(N), warp tile 64x32.
__global__ __launch_bounds__(256, 1)
void gemm_kernel(float* __restrict__ out, const float* __restrict__ bias) {
    extern __shared__ char smem[];
    const uint32_t sb = smem_u32(smem);
    const uint32_t TILE0 = (sb + 1023) & ~1023u;

    const int tid = threadIdx.x;
    const int wid = tid >> 5, lid = tid & 31;
    const int warp_m = wid & 1;    // 0..1 (64 rows each)
    const int warp_n = wid >> 1;   // 0..3 (32 cols each)

    const int t  = blockIdx.x;
    const int bm = ((t >> 9) << 3) | (t & 7);   // 8-wide M supertiles for B reuse in L2
    const int bn = (t >> 3) & 63;

    const char* gA = (const char*)(g_A + (size_t)bm * 128 * KP);
    const char* gB = (const char*)(g_B + (size_t)bn * 128 * KP);

    const int lrow = tid >> 3;      // 0..31
    const int lseg = tid & 7;       // 16B segment within 128B row

    // ---- stage loader: Ahi, Alo, Bhi, Blo tiles (16KB each) ----
    auto load_stage = [&](int j, int slot) {
        const uint32_t s0 = TILE0 + slot * SMEM_STAGE;
        const size_t kb_hi = (size_t)(j * BK) * 2;          // byte offset of hi chunk
        const size_t kb_lo = (size_t)(2048 + j * BK) * 2;   // byte offset of lo chunk
        #pragma unroll
        for (int i = 0; i < 4; i++) {
            const int row = lrow + i * 32;
            const uint32_t so = SWZ((uint32_t)(row * 128 + lseg * 16));
            const size_t go = (size_t)row * (KP * 2) + lseg * 16;
            cpasync16(s0 +         so, gA + go + kb_hi);
            cpasync16(s0 + 16384 + so, gA + go + kb_lo);
            cpasync16(s0 + 32768 + so, gB + go + kb_hi);
            cpasync16(s0 + 49152 + so, gB + go + kb_lo);
        }
        cp_commit();
    };

    float acc[4][4][4];
    #pragma unroll
    for (int a = 0; a < 4; a++)
        #pragma unroll
        for (int b = 0; b < 4; b++)
            #pragma unroll
            for (int c = 0; c < 4; c++) acc[a][b][c] = 0.f;

    // ldmatrix lane address components
    const int laneA_row = (lid & 7) + ((lid >> 3) & 1) * 8;  // within 16-row tile
    const int laneA_k8  = ((lid >> 4) & 1) * 8;
    const int laneB_row = (lid & 7) + ((lid >> 4) & 1) * 8;  // within 16-n block
    const int laneB_k8  = ((lid >> 3) & 1) * 8;

    // prologue
    load_stage(0, 0);
    load_stage(1, 1);

    #pragma unroll 1
    for (int j = 0; j < NITER; j++) {
        cp_wait1();
        __syncthreads();
        if (j + 2 < NITER) load_stage(j + 2, (j + 2) % NSTAGE);
        else cp_commit();  // empty group keeps wait_group accounting valid

        const uint32_t s0 = TILE0 + (j % NSTAGE) * SMEM_STAGE;
        const uint32_t aH = s0, aL = s0 + 16384, bH = s0 + 32768, bL = s0 + 49152;

        #pragma unroll
        for (int ks = 0; ks < 4; ks++) {
            uint32_t ah[4][4], al[4][4], bh[2][4], bl[2][4];
            #pragma unroll
            for (int mt = 0; mt < 4; mt++) {
                const uint32_t off = SWZ((uint32_t)((warp_m * 64 + mt * 16 + laneA_row) * 128
                                                    + (ks * 16 + laneA_k8) * 2));
                ldm4(ah[mt], aH + off);
                ldm4(al[mt], aL + off);
            }
            #pragma unroll
            for (int bt = 0; bt < 2; bt++) {
                const uint32_t off = SWZ((uint32_t)((warp_n * 32 + bt * 16 + laneB_row) * 128
                                                    + (ks * 16 + laneB_k8) * 2));
                ldm4(bh[bt], bH + off);
                ldm4(bl[bt], bL + off);
            }
            #pragma unroll
            for (int mt = 0; mt < 4; mt++)
                #pragma unroll
                for (int nt = 0; nt < 4; nt++) {
                    const uint32_t b0h = bh[nt >> 1][(nt & 1) * 2];
                    const uint32_t b1h = bh[nt >> 1][(nt & 1) * 2 + 1];
                    const uint32_t b0l = bl[nt >> 1][(nt & 1) * 2];
                    const uint32_t b1l = bl[nt >> 1][(nt & 1) * 2 + 1];
                    mma16816(acc[mt][nt], ah[mt], b0h, b1h);  // hi*hi
                    mma16816(acc[mt][nt], al[mt], b0h, b1h);  // lo*hi
                    mma16816(acc[mt][nt], ah[mt], b0l, b1l);  // hi*lo
                }
        }
    }

    // ---- epilogue: add bias, store fp32 ----
    const int gm0 = bm * 128 + warp_m * 64 + (lid >> 2);
    const int gn0 = bn * 128 + warp_n * 32 + (lid & 3) * 2;
    #pragma unroll
    for (int nt = 0; nt < 4; nt++) {
        const int gn = gn0 + nt * 8;
        const float2 bv = *(const float2*)(bias + gn);
        #pragma unroll
        for (int mt = 0; mt < 4; mt++) {
            const int gm = gm0 + mt * 16;
            float2 v0, v1;
            v0.x = acc[mt][nt][0] + bv.x;  v0.y = acc[mt][nt][1] + bv.y;
            v1.x = acc[mt][nt][2] + bv.x;  v1.y = acc[mt][nt][3] + bv.y;
            *(float2*)(out + (size_t)gm * NF_DIM + gn)       = v0;
            *(float2*)(out + (size_t)(gm + 8) * NF_DIM + gn) = v1;
        }
    }
}

// ---------------- launch ----------------
extern "C" void kernel_launch(void* const* d_in, const int* in_sizes, int n_in,
                              void* d_out, int out_size) {
    const float* x      = (const float*)d_in[0];
    const int*   packed = (const int*)d_in[1];
    const float* scales = (const float*)d_in[2];
    const int*   zeros  = (const int*)d_in[3];
    const float* bias   = (const float*)d_in[4];
    float*       out    = (float*)d_out;

    cudaFuncSetAttribute(gemm_kernel, cudaFuncAttributeMaxDynamicSharedMemorySize, SMEM_BYTES);

    prep_x_kernel<<<(M_DIM * NX_DIM) / 4 / 256, 256>>>(x);
    prep_w_kernel<<<(NF_DIM * (NX_DIM / 2)) / 256, 256>>>(packed, scales, zeros);
    gemm_kernel<<<64 * 64, 256, SMEM_BYTES>>>(out, bias);
}